// round 2
// baseline (speedup 1.0000x reference)
#include <cuda_runtime.h>
#include <math.h>

#define BB 4096
#define LL 200
#define DD 128
#define NH 4
#define HS_STRIDE 201   // odd stride -> conflict-free both access directions

// Scratch (device globals; no allocation at runtime)
__device__ float g_P[DD * 512];   // P[j][c], c = h*128 + i, includes 1/sqrt(32)
__device__ float g_G[512 * DD];   // G[c][j]
__device__ float g_R[BB * 512];   // R[b][c]
__device__ float g_U[BB * 512];   // U[b][c]

// ---------------------------------------------------------------------------
// K0: P[j, h*128+i] = (1/s) * sum_{t<32} Wq[32h+t, j] * Wk[32h+t, i]
//     G[h*128+i, j] =          sum_{t<32} Wv[32h+t, i] * Wo[j, 32h+t]
// ---------------------------------------------------------------------------
__global__ __launch_bounds__(256) void k0_prep(
    const float* __restrict__ Wq, const float* __restrict__ Wk,
    const float* __restrict__ Wv, const float* __restrict__ Wo) {
    const float inv_scale = 0.17677669529663687f;  // 1/sqrt(32)
    int gid = blockIdx.x * blockDim.x + threadIdx.x;
    if (gid < DD * 512) {
        int j = gid >> 9;
        int c = gid & 511;
        int h = c >> 7, i = c & 127;
        int ob = h * 32;
        float s = 0.f;
        #pragma unroll
        for (int t = 0; t < 32; t++) {
            int o = ob + t;
            s += Wq[o * DD + j] * Wk[o * DD + i];
        }
        g_P[j * 512 + c] = s * inv_scale;
    } else {
        int idx = gid - DD * 512;
        int c = idx >> 7;
        int j = idx & 127;
        int h = c >> 7, i = c & 127;
        int ob = h * 32;
        float s = 0.f;
        #pragma unroll
        for (int t = 0; t < 32; t++) {
            int o = ob + t;
            s += Wv[o * DD + i] * Wo[j * DD + o];
        }
        g_G[c * DD + j] = s;
    }
}

// ---------------------------------------------------------------------------
// Tiled fp32 GEMM: C[M,N] = A[M,K] @ B[K,N], row-major.
// Tile 64x64, BK=16, 256 threads, 4x4 per thread. M,N % 64 == 0, K % 16 == 0.
// ---------------------------------------------------------------------------
__global__ __launch_bounds__(256) void gemm64(
    const float* __restrict__ A, const float* __restrict__ Bm,
    float* __restrict__ C, int M, int N, int K) {
    __shared__ __align__(16) float As[16 * 68];
    __shared__ __align__(16) float Bs[16 * 64];

    int tid = threadIdx.x;
    int tx = tid & 15, ty = tid >> 4;
    int m0 = blockIdx.y * 64, n0 = blockIdx.x * 64;
    int aRow = tid >> 2;          // 0..63
    int aK4  = (tid & 3) * 4;     // 0,4,8,12
    int bRow = tid >> 6;          // 0..3
    int bCol = tid & 63;

    float acc[4][4] = {};

    for (int k0 = 0; k0 < K; k0 += 16) {
        float4 av = *(const float4*)&A[(size_t)(m0 + aRow) * K + k0 + aK4];
        float bv[4];
        #pragma unroll
        for (int p = 0; p < 4; p++)
            bv[p] = Bm[(size_t)(k0 + bRow + p * 4) * N + n0 + bCol];

        __syncthreads();
        As[(aK4 + 0) * 68 + aRow] = av.x;
        As[(aK4 + 1) * 68 + aRow] = av.y;
        As[(aK4 + 2) * 68 + aRow] = av.z;
        As[(aK4 + 3) * 68 + aRow] = av.w;
        #pragma unroll
        for (int p = 0; p < 4; p++)
            Bs[(bRow + p * 4) * 64 + bCol] = bv[p];
        __syncthreads();

        #pragma unroll
        for (int kk = 0; kk < 16; kk++) {
            float4 a  = *(const float4*)&As[kk * 68 + ty * 4];
            float4 bq = *(const float4*)&Bs[kk * 64 + tx * 4];
            acc[0][0] += a.x * bq.x; acc[0][1] += a.x * bq.y;
            acc[0][2] += a.x * bq.z; acc[0][3] += a.x * bq.w;
            acc[1][0] += a.y * bq.x; acc[1][1] += a.y * bq.y;
            acc[1][2] += a.y * bq.z; acc[1][3] += a.y * bq.w;
            acc[2][0] += a.z * bq.x; acc[2][1] += a.z * bq.y;
            acc[2][2] += a.z * bq.z; acc[2][3] += a.z * bq.w;
            acc[3][0] += a.w * bq.x; acc[3][1] += a.w * bq.y;
            acc[3][2] += a.w * bq.z; acc[3][3] += a.w * bq.w;
        }
    }

    #pragma unroll
    for (int r = 0; r < 4; r++) {
        float4 v = make_float4(acc[r][0], acc[r][1], acc[r][2], acc[r][3]);
        *(float4*)&C[(size_t)(m0 + ty * 4 + r) * N + n0 + tx * 4] = v;
    }
}

// ---------------------------------------------------------------------------
// Main attention kernel: one CTA per batch row.
//   scores[h,l] = H[l,:] . r_h   (r from g_R)
//   masked softmax over l per head
//   U[h,i] = sum_l attn[h,l] * H[l,i]  -> g_U
// H staged transposed in smem (stride 201) so both phases are conflict-free.
// ---------------------------------------------------------------------------
__global__ __launch_bounds__(256) void attn_kernel(
    const float* __restrict__ Hist, const int* __restrict__ Mask) {
    extern __shared__ float Hs[];                   // [128][HS_STRIDE]
    __shared__ __align__(16) float sbuf[4 * LL];    // scores, then attn as float4[200]
    __shared__ __align__(16) float4 rs[DD];         // rs[i] = (r0,r1,r2,r3)[i]
    __shared__ float u_part[512];

    int b = blockIdx.x;
    int tid = threadIdx.x;

    // load R (transposed into float4-per-i)
    for (int t = tid; t < 512; t += 256) {
        int h = t >> 7, i = t & 127;
        ((float*)rs)[i * 4 + h] = g_R[(size_t)b * 512 + t];
    }

    // load H transposed: Hs[i][l]
    const float* Hb = Hist + (size_t)b * (LL * DD);
    for (int idx = tid; idx < LL * DD; idx += 256) {
        int l = idx >> 7;
        int i = idx & 127;
        Hs[i * HS_STRIDE + l] = Hb[idx];
    }
    __syncthreads();

    // phase 1: scores
    if (tid < LL) {
        int l = tid;
        float s0 = 0.f, s1 = 0.f, s2 = 0.f, s3 = 0.f;
        #pragma unroll 4
        for (int i = 0; i < DD; i++) {
            float hv = Hs[i * HS_STRIDE + l];
            float4 rv = rs[i];
            s0 += hv * rv.x; s1 += hv * rv.y;
            s2 += hv * rv.z; s3 += hv * rv.w;
        }
        if (Mask[(size_t)b * LL + l] == 0) {
            s0 = s1 = s2 = s3 = -1e30f;
        }
        sbuf[0 * LL + l] = s0; sbuf[1 * LL + l] = s1;
        sbuf[2 * LL + l] = s2; sbuf[3 * LL + l] = s3;
    }
    __syncthreads();

    // softmax per head (warps 0..3)
    int wid = tid >> 5, lane = tid & 31;
    if (wid < NH) {
        float m = -3.4e38f;
        for (int l = lane; l < LL; l += 32) m = fmaxf(m, sbuf[wid * LL + l]);
        #pragma unroll
        for (int o = 16; o; o >>= 1) m = fmaxf(m, __shfl_xor_sync(0xffffffffu, m, o));
        float sum = 0.f;
        for (int l = lane; l < LL; l += 32) {
            float e = expf(sbuf[wid * LL + l] - m);
            sbuf[wid * LL + l] = e;
            sum += e;
        }
        #pragma unroll
        for (int o = 16; o; o >>= 1) sum += __shfl_xor_sync(0xffffffffu, sum, o);
        float inv = 1.0f / sum;
        for (int l = lane; l < LL; l += 32) sbuf[wid * LL + l] *= inv;
    }
    __syncthreads();

    // repack attn into float4-per-l (in place over sbuf)
    float a0 = 0.f, a1 = 0.f, a2 = 0.f, a3 = 0.f;
    if (tid < LL) {
        a0 = sbuf[0 * LL + tid]; a1 = sbuf[1 * LL + tid];
        a2 = sbuf[2 * LL + tid]; a3 = sbuf[3 * LL + tid];
    }
    __syncthreads();
    float4* a4 = (float4*)sbuf;
    if (tid < LL) a4[tid] = make_float4(a0, a1, a2, a3);
    __syncthreads();

    // phase 2: U[h,i] = sum_l attn[h,l] * H[l,i]
    int i = tid & 127, grp = tid >> 7;
    float u0 = 0.f, u1 = 0.f, u2 = 0.f, u3 = 0.f;
    for (int l = grp; l < LL; l += 2) {
        float hv = Hs[i * HS_STRIDE + l];
        float4 av = a4[l];
        u0 += av.x * hv; u1 += av.y * hv;
        u2 += av.z * hv; u3 += av.w * hv;
    }
    if (grp == 1) {
        u_part[0 * 128 + i] = u0; u_part[1 * 128 + i] = u1;
        u_part[2 * 128 + i] = u2; u_part[3 * 128 + i] = u3;
    }
    __syncthreads();
    if (grp == 0) {
        float* Ub = g_U + (size_t)b * 512;
        Ub[0 * 128 + i] = u0 + u_part[0 * 128 + i];
        Ub[1 * 128 + i] = u1 + u_part[1 * 128 + i];
        Ub[2 * 128 + i] = u2 + u_part[2 * 128 + i];
        Ub[3 * 128 + i] = u3 + u_part[3 * 128 + i];
    }
}

// ---------------------------------------------------------------------------
extern "C" void kernel_launch(void* const* d_in, const int* in_sizes, int n_in,
                              void* d_out, int out_size) {
    const float* X    = (const float*)d_in[0];   // target_item [4096,128]
    const float* Hist = (const float*)d_in[1];   // history [4096,200,128]
    const int*   Mask = (const int*)d_in[2];     // mask [4096,200]
    const float* Wq   = (const float*)d_in[3];
    const float* Wk   = (const float*)d_in[4];
    const float* Wv   = (const float*)d_in[5];
    const float* Wo   = (const float*)d_in[6];
    float* Y = (float*)d_out;                    // [4096,128]

    float *pP, *pG, *pR, *pU;
    cudaGetSymbolAddress((void**)&pP, g_P);
    cudaGetSymbolAddress((void**)&pG, g_G);
    cudaGetSymbolAddress((void**)&pR, g_R);
    cudaGetSymbolAddress((void**)&pU, g_U);

    const int attn_smem = DD * HS_STRIDE * (int)sizeof(float);  // 102912
    cudaFuncSetAttribute(attn_kernel,
                         cudaFuncAttributeMaxDynamicSharedMemorySize, attn_smem);

    // K0: precompute P and G (131072 outputs)
    k0_prep<<<512, 256>>>(Wq, Wk, Wv, Wo);

    // R = X @ P : [4096,128] x [128,512]
    gemm64<<<dim3(512 / 64, BB / 64), 256>>>(X, pP, pR, BB, 512, DD);

    // attention core
    attn_kernel<<<BB, 256, attn_smem>>>(Hist, Mask);

    // Y = U @ G : [4096,512] x [512,128]
    gemm64<<<dim3(DD / 64, BB / 64), 256>>>(pU, pG, Y, BB, DD, 512);
}

// round 3
// speedup vs baseline: 1.6917x; 1.6917x over previous
#include <cuda_runtime.h>
#include <math.h>
#include <stdint.h>

#define BB 4096
#define LL 200
#define DD 128
#define NH 4

// Scratch (device globals; no runtime allocation)
__device__ float g_P[DD * 512];   // P[j][c], c = h*128 + i, includes 1/sqrt(32)
__device__ float g_G[512 * DD];   // G[c][j]
__device__ float g_R[BB * 512];   // R[b][c]; reused as split-K partials for Y
__device__ float g_U[BB * 512];   // U[b][c]

__device__ __forceinline__ uint32_t smem_u32(const void* p) {
    return (uint32_t)__cvta_generic_to_shared(p);
}

// ---------------------------------------------------------------------------
// K0: P[j, h*128+i] = (1/s) * sum_{t<32} Wq[32h+t, j] * Wk[32h+t, i]
//     G[h*128+i, j] =          sum_{t<32} Wv[32h+t, i] * Wo[j, 32h+t]
// ---------------------------------------------------------------------------
__global__ __launch_bounds__(256) void k0_prep(
    const float* __restrict__ Wq, const float* __restrict__ Wk,
    const float* __restrict__ Wv, const float* __restrict__ Wo) {
    const float inv_scale = 0.17677669529663687f;  // 1/sqrt(32)
    int gid = blockIdx.x * blockDim.x + threadIdx.x;
    if (gid < DD * 512) {
        int j = gid >> 9;
        int c = gid & 511;
        int h = c >> 7, i = c & 127;
        int ob = h * 32;
        float s = 0.f;
        #pragma unroll
        for (int t = 0; t < 32; t++) {
            int o = ob + t;
            s += Wq[o * DD + j] * Wk[o * DD + i];
        }
        g_P[j * 512 + c] = s * inv_scale;
    } else {
        int idx = gid - DD * 512;
        int c = idx >> 7;
        int j = idx & 127;
        int h = c >> 7, i = c & 127;
        int ob = h * 32;
        float s = 0.f;
        #pragma unroll
        for (int t = 0; t < 32; t++) {
            int o = ob + t;
            s += Wv[o * DD + i] * Wo[j * DD + o];
        }
        g_G[c * DD + j] = s;
    }
}

// ---------------------------------------------------------------------------
// Tiled fp32 GEMM: C[M,N] = A[M,K](lda) @ B[K,N], row-major, with z-slab
// offsets for split-K use. Tile 64x64, BK=16, 256 threads, 4x4 per thread.
// ---------------------------------------------------------------------------
__global__ __launch_bounds__(256) void gemm64(
    const float* __restrict__ A, const float* __restrict__ Bm,
    float* __restrict__ C, int M, int N, int K, int lda,
    long sAz, long sBz, long sCz) {
    A  += (long)blockIdx.z * sAz;
    Bm += (long)blockIdx.z * sBz;
    C  += (long)blockIdx.z * sCz;

    __shared__ __align__(16) float As[16 * 68];
    __shared__ __align__(16) float Bs[16 * 64];

    int tid = threadIdx.x;
    int tx = tid & 15, ty = tid >> 4;
    int m0 = blockIdx.y * 64, n0 = blockIdx.x * 64;
    int aRow = tid >> 2;          // 0..63
    int aK4  = (tid & 3) * 4;     // 0,4,8,12
    int bRow = tid >> 6;          // 0..3
    int bCol = tid & 63;

    float acc[4][4] = {};

    for (int k0 = 0; k0 < K; k0 += 16) {
        float4 av = *(const float4*)&A[(size_t)(m0 + aRow) * lda + k0 + aK4];
        float bv[4];
        #pragma unroll
        for (int p = 0; p < 4; p++)
            bv[p] = Bm[(size_t)(k0 + bRow + p * 4) * N + n0 + bCol];

        __syncthreads();
        As[(aK4 + 0) * 68 + aRow] = av.x;
        As[(aK4 + 1) * 68 + aRow] = av.y;
        As[(aK4 + 2) * 68 + aRow] = av.z;
        As[(aK4 + 3) * 68 + aRow] = av.w;
        #pragma unroll
        for (int p = 0; p < 4; p++)
            Bs[(bRow + p * 4) * 64 + bCol] = bv[p];
        __syncthreads();

        #pragma unroll
        for (int kk = 0; kk < 16; kk++) {
            float4 a  = *(const float4*)&As[kk * 68 + ty * 4];
            float4 bq = *(const float4*)&Bs[kk * 64 + tx * 4];
            acc[0][0] += a.x * bq.x; acc[0][1] += a.x * bq.y;
            acc[0][2] += a.x * bq.z; acc[0][3] += a.x * bq.w;
            acc[1][0] += a.y * bq.x; acc[1][1] += a.y * bq.y;
            acc[1][2] += a.y * bq.z; acc[1][3] += a.y * bq.w;
            acc[2][0] += a.z * bq.x; acc[2][1] += a.z * bq.y;
            acc[2][2] += a.z * bq.z; acc[2][3] += a.z * bq.w;
            acc[3][0] += a.w * bq.x; acc[3][1] += a.w * bq.y;
            acc[3][2] += a.w * bq.z; acc[3][3] += a.w * bq.w;
        }
    }

    #pragma unroll
    for (int r = 0; r < 4; r++) {
        float4 v = make_float4(acc[r][0], acc[r][1], acc[r][2], acc[r][3]);
        *(float4*)&C[(size_t)(m0 + ty * 4 + r) * N + n0 + tx * 4] = v;
    }
}

// ---------------------------------------------------------------------------
// Final reduce for split-K: Y = sum_z partial[z], z = 0..3
// ---------------------------------------------------------------------------
__global__ __launch_bounds__(256) void reduce4(
    const float4* __restrict__ P, float4* __restrict__ Y) {
    int i = blockIdx.x * blockDim.x + threadIdx.x;  // 0..131071
    const int S = BB * DD / 4;                       // 131072
    float4 a = P[i], b = P[i + S], c = P[i + 2 * S], d = P[i + 3 * S];
    float4 o;
    o.x = (a.x + b.x) + (c.x + d.x);
    o.y = (a.y + b.y) + (c.y + d.y);
    o.z = (a.z + b.z) + (c.z + d.z);
    o.w = (a.w + b.w) + (c.w + d.w);
    Y[i] = o;
}

// ---------------------------------------------------------------------------
// Attention core: one CTA per batch row, 256 threads.
// H staged in smem as float4 with XOR swizzle: Hs4[l*32 + (c4 ^ (l&31))].
// Conflict-free 128-bit LDS in both row-dot and column-sum directions.
//   phase 1: score[h,l] = H[l,:] . r_h
//   softmax (masked) per head
//   phase 2: U[h,i] = sum_l attn[h,l] * H[l,i]
// ---------------------------------------------------------------------------
__global__ __launch_bounds__(256) void attn_kernel(
    const float4* __restrict__ Hist4, const int* __restrict__ Mask) {
    extern __shared__ __align__(16) float4 Hs4[];      // 200*32 float4 = 102400 B
    __shared__ __align__(16) float sbuf[NH * LL];      // scores -> attn in place
    __shared__ __align__(16) float rq[NH * DD];        // r[h][i]
    __shared__ __align__(16) float upart[512];

    int b = blockIdx.x;
    int tid = threadIdx.x;

    // Stage H via cp.async, swizzled
    const float4* Hb = Hist4 + (size_t)b * (LL * 32);
    #pragma unroll 5
    for (int idx = tid; idx < LL * 32; idx += 256) {
        int l = idx >> 5, c = idx & 31;
        uint32_t dst = smem_u32(&Hs4[l * 32 + (c ^ (l & 31))]);
        asm volatile("cp.async.cg.shared.global [%0], [%1], 16;\n"
                     :: "r"(dst), "l"(Hb + idx));
    }
    asm volatile("cp.async.commit_group;\n" ::: "memory");

    // Load R while cp.async is in flight
    if (tid < 128) {
        const float4* Rb = (const float4*)(g_R + (size_t)b * 512);
        ((float4*)rq)[tid] = Rb[tid];
    }
    int mval = 1;
    if (tid < LL) mval = Mask[(size_t)b * LL + tid];

    asm volatile("cp.async.wait_group 0;\n" ::: "memory");
    __syncthreads();

    // Phase 1: scores (one thread per l)
    if (tid < LL) {
        int l = tid, swz = l & 31;
        float s0 = 0.f, s1 = 0.f, s2 = 0.f, s3 = 0.f;
        const float4* rq4 = (const float4*)rq;
        #pragma unroll 8
        for (int i4 = 0; i4 < 32; i4++) {
            float4 hv = Hs4[l * 32 + (i4 ^ swz)];
            float4 r0 = rq4[0 * 32 + i4];
            float4 r1 = rq4[1 * 32 + i4];
            float4 r2 = rq4[2 * 32 + i4];
            float4 r3 = rq4[3 * 32 + i4];
            s0 += hv.x * r0.x + hv.y * r0.y + hv.z * r0.z + hv.w * r0.w;
            s1 += hv.x * r1.x + hv.y * r1.y + hv.z * r1.z + hv.w * r1.w;
            s2 += hv.x * r2.x + hv.y * r2.y + hv.z * r2.z + hv.w * r2.w;
            s3 += hv.x * r3.x + hv.y * r3.y + hv.z * r3.z + hv.w * r3.w;
        }
        if (mval == 0) { s0 = s1 = s2 = s3 = -1e30f; }
        sbuf[0 * LL + l] = s0; sbuf[1 * LL + l] = s1;
        sbuf[2 * LL + l] = s2; sbuf[3 * LL + l] = s3;
    }
    __syncthreads();

    // Softmax per head (warps 0..3), attn left in sbuf
    int wid = tid >> 5, lane = tid & 31;
    if (wid < NH) {
        float m = -3.4e38f;
        for (int l = lane; l < LL; l += 32) m = fmaxf(m, sbuf[wid * LL + l]);
        #pragma unroll
        for (int o = 16; o; o >>= 1) m = fmaxf(m, __shfl_xor_sync(0xffffffffu, m, o));
        float sum = 0.f;
        for (int l = lane; l < LL; l += 32) {
            float e = expf(sbuf[wid * LL + l] - m);
            sbuf[wid * LL + l] = e;
            sum += e;
        }
        #pragma unroll
        for (int o = 16; o; o >>= 1) sum += __shfl_xor_sync(0xffffffffu, sum, o);
        float inv = 1.0f / sum;
        for (int l = lane; l < LL; l += 32) sbuf[wid * LL + l] *= inv;
    }
    __syncthreads();

    // Phase 2: U[h, 4*c4..4*c4+3] accumulated as float4.
    // tid = grp*128 + h*32 + c4; grp in {0,1} strides over l.
    int c4 = tid & 31, h = (tid >> 5) & 3, grp = tid >> 7;
    float4 acc = make_float4(0.f, 0.f, 0.f, 0.f);
    for (int l = grp; l < LL; l += 2) {
        float a = sbuf[h * LL + l];
        float4 hv = Hs4[l * 32 + (c4 ^ (l & 31))];
        acc.x += a * hv.x; acc.y += a * hv.y;
        acc.z += a * hv.z; acc.w += a * hv.w;
    }
    if (grp == 1) ((float4*)upart)[h * 32 + c4] = acc;
    __syncthreads();
    if (grp == 0) {
        float4 o = ((float4*)upart)[h * 32 + c4];
        acc.x += o.x; acc.y += o.y; acc.z += o.z; acc.w += o.w;
        ((float4*)(g_U + (size_t)b * 512))[h * 32 + c4] = acc;
    }
}

// ---------------------------------------------------------------------------
extern "C" void kernel_launch(void* const* d_in, const int* in_sizes, int n_in,
                              void* d_out, int out_size) {
    const float* X    = (const float*)d_in[0];   // target_item [4096,128]
    const float* Hist = (const float*)d_in[1];   // history [4096,200,128]
    const int*   Mask = (const int*)d_in[2];     // mask [4096,200]
    const float* Wq   = (const float*)d_in[3];
    const float* Wk   = (const float*)d_in[4];
    const float* Wv   = (const float*)d_in[5];
    const float* Wo   = (const float*)d_in[6];
    float* Y = (float*)d_out;                    // [4096,128]

    float *pP, *pG, *pR, *pU;
    cudaGetSymbolAddress((void**)&pP, g_P);
    cudaGetSymbolAddress((void**)&pG, g_G);
    cudaGetSymbolAddress((void**)&pR, g_R);
    cudaGetSymbolAddress((void**)&pU, g_U);

    const int attn_smem = LL * 32 * (int)sizeof(float4);  // 102400
    cudaFuncSetAttribute(attn_kernel,
                         cudaFuncAttributeMaxDynamicSharedMemorySize, attn_smem);

    // K0: precompute P and G
    k0_prep<<<512, 256>>>(Wq, Wk, Wv, Wo);

    // R = X @ P : [4096,128] x [128,512]
    gemm64<<<dim3(512 / 64, BB / 64, 1), 256>>>(X, pP, pR, BB, 512, DD, DD, 0, 0, 0);

    // attention core (reads g_R, writes g_U)
    attn_kernel<<<BB, 256, attn_smem>>>((const float4*)Hist, Mask);

    // Y = U @ G via split-K x4: partials into g_R (dead after attn)
    gemm64<<<dim3(DD / 64, BB / 64, 4), 256>>>(
        pU, pG, pR, BB, DD, DD, 512,
        /*sAz=*/128, /*sBz=*/(long)128 * DD, /*sCz=*/(long)BB * DD);

    // Y = sum of 4 partial slabs
    reduce4<<<BB * DD / 4 / 256, 256>>>((const float4*)pR, (float4*)Y);
}